// round 11
// baseline (speedup 1.0000x reference)
#include <cuda_runtime.h>
#include <cuda_bf16.h>
#include <cstdint>

// Problem constants
#define BATCH 64
#define NPTS  512
#define CH    1024
#define KNN   32

// GEMM geometry: 128x128 CTA tile, 16 warps of 32x32, k-chunk 16
#define KC    16
#define NK0   (CH / KC)        // 64
#define SROWB 48               // smem row stride bytes (16 bf16 + 8 pad)
#define TILEB (128 * SROWB)    // 6144 B per split tile

// Scratch (__device__ globals; no allocation)
__device__ float g_S[(size_t)BATCH * NPTS * NPTS];          // 64 MB
__device__ __nv_bfloat16 g_hi[(size_t)BATCH * NPTS * CH];
__device__ __nv_bfloat16 g_md[(size_t)BATCH * NPTS * CH];
__device__ __nv_bfloat16 g_lo[(size_t)BATCH * NPTS * CH];
__device__ float g_thr[BATCH * NPTS];
__device__ float g_dinv[BATCH * NPTS];

// tri tile decode: 10 tiles over 4x4, bi<=bj
__device__ __forceinline__ void tri_decode(int t, int& bi, int& bj) {
    bi = (t >= 4) + (t >= 7) + (t >= 9);
    const int start = bi * 4 - ((bi * (bi - 1)) >> 1);
    bj = bi + (t - start);
}

__device__ __forceinline__ void ldsm_x4(uint32_t* r, uint32_t addr) {
    asm volatile("ldmatrix.sync.aligned.m8n8.x4.shared.b16 {%0,%1,%2,%3}, [%4];"
                 : "=r"(r[0]), "=r"(r[1]), "=r"(r[2]), "=r"(r[3]) : "r"(addr));
}
__device__ __forceinline__ void mma16816(float* d, const uint32_t* a,
                                         uint32_t b0, uint32_t b1) {
    asm volatile(
        "mma.sync.aligned.m16n8k16.row.col.f32.bf16.bf16.f32 "
        "{%0,%1,%2,%3}, {%4,%5,%6,%7}, {%8,%9}, {%0,%1,%2,%3};"
        : "+f"(d[0]), "+f"(d[1]), "+f"(d[2]), "+f"(d[3])
        : "r"(a[0]), "r"(a[1]), "r"(a[2]), "r"(a[3]), "r"(b0), "r"(b1));
}

// ---------------------------------------------------------------------------
// Kernel 0: split x into bf16 hi/mid/lo (residuals exact in fp32)
// ---------------------------------------------------------------------------
__global__ __launch_bounds__(256) void convert_kernel(const float* __restrict__ x) {
    const size_t base = ((size_t)blockIdx.x * 256 + threadIdx.x) * 8;
    float v[8];
    *(float4*)&v[0] = *(const float4*)(x + base);
    *(float4*)&v[4] = *(const float4*)(x + base + 4);

    __nv_bfloat16 h[8], m[8], l[8];
#pragma unroll
    for (int i = 0; i < 8; i++) {
        h[i] = __float2bfloat16(v[i]);
        float r1 = v[i] - __bfloat162float(h[i]);
        m[i] = __float2bfloat16(r1);
        float r2 = r1 - __bfloat162float(m[i]);
        l[i] = __float2bfloat16(r2);
    }
    *(uint4*)(g_hi + base) = *(uint4*)h;
    *(uint4*)(g_md + base) = *(uint4*)m;
    *(uint4*)(g_lo + base) = *(uint4*)l;
}

// ---------------------------------------------------------------------------
// Kernel 1: S tri-tile via mma.sync bf16, 6-GEMM split with GROUPED
// accumulators: Ghh holds hi*hi alone (only 64 large-magnitude adds ->
// rounding walk at the fp32 ulp floor); Grest holds the 5 small-scale GEMMs
// (partial sums <= 0.07 -> rounding negligible). S = Ghh + Grest (1 add).
// grid = (10, 64), block = 512 (16 warps as 4x4 of 32x32 warp tiles).
// ---------------------------------------------------------------------------
__global__ __launch_bounds__(512) void xxt_mma_kernel() {
    __shared__ __align__(16) unsigned char smem[6 * TILEB];   // 36864 B

    const int tid = threadIdx.x;
    const int wid = tid >> 5;
    const int lane = tid & 31;
    const int wm = wid >> 2;          // 0..3  (32-row band)
    const int wn = wid & 3;           // 0..3  (32-col band)

    int bi, bj;
    tri_decode((int)blockIdx.x, bi, bj);
    const int b = blockIdx.y;
    const int ti = bi * 128;
    const int tj = bj * 128;

    const __nv_bfloat16* sp[6];
    {
        const size_t bo = (size_t)b * NPTS * CH;
        sp[0] = g_hi + bo + (size_t)ti * CH;
        sp[1] = g_md + bo + (size_t)ti * CH;
        sp[2] = g_lo + bo + (size_t)ti * CH;
        sp[3] = g_hi + bo + (size_t)tj * CH;
        sp[4] = g_md + bo + (size_t)tj * CH;
        sp[5] = g_lo + bo + (size_t)tj * CH;
    }

    const uint32_t sb = (uint32_t)__cvta_generic_to_shared(smem);
    const int lrow = lane & 15;
    const int lhalf = lane >> 4;
    const uint32_t a_base = sb + (uint32_t)((wm * 32 + lrow) * SROWB + lhalf * 16);
    const uint32_t b_base = sb + 3 * TILEB + (uint32_t)((wn * 32 + lrow) * SROWB + lhalf * 16);

    // two accumulator groups: [mt 0..1][nt 0..3][4]
    float ghh[2][4][4], grest[2][4][4];
#pragma unroll
    for (int mt = 0; mt < 2; mt++)
#pragma unroll
        for (int nt = 0; nt < 4; nt++)
#pragma unroll
            for (int r = 0; r < 4; r++) { ghh[mt][nt][r] = 0.f; grest[mt][nt][r] = 0.f; }

    for (int k0 = 0; k0 < NK0; k0++) {
        // load 6 tiles (128 rows x 16 bf16): 1536 uint4 / 512 threads = 3 each
#pragma unroll
        for (int p = 0; p < 3; p++) {
            const int fid = tid + p * 512;
            const int t = fid >> 8;            // 0..5
            const int r = (fid >> 1) & 127;
            const int half = fid & 1;
            uint4 v = *(const uint4*)(sp[t] + (size_t)r * CH + k0 * KC + half * 8);
            *(uint4*)(smem + t * TILEB + r * SROWB + half * 16) = v;
        }
        __syncthreads();

        // A fragments for all 3 splits (hi, md, lo)
        uint32_t afr[3][2][4];
#pragma unroll
        for (int s = 0; s < 3; s++) {
            ldsm_x4(afr[s][0], a_base + s * TILEB);
            ldsm_x4(afr[s][1], a_base + s * TILEB + 16 * SROWB);
        }

        // B-hi: pairs (hi,hi)->Ghh, (md,hi)->Grest, (lo,hi)->Grest
        {
            uint32_t bfr[2][4];
            ldsm_x4(bfr[0], b_base);
            ldsm_x4(bfr[1], b_base + 16 * SROWB);
#pragma unroll
            for (int bg = 0; bg < 2; bg++)
#pragma unroll
                for (int mt = 0; mt < 2; mt++) {
                    mma16816(ghh[mt][bg * 2 + 0], afr[0][mt], bfr[bg][0], bfr[bg][2]);
                    mma16816(ghh[mt][bg * 2 + 1], afr[0][mt], bfr[bg][1], bfr[bg][3]);
                    mma16816(grest[mt][bg * 2 + 0], afr[1][mt], bfr[bg][0], bfr[bg][2]);
                    mma16816(grest[mt][bg * 2 + 1], afr[1][mt], bfr[bg][1], bfr[bg][3]);
                    mma16816(grest[mt][bg * 2 + 0], afr[2][mt], bfr[bg][0], bfr[bg][2]);
                    mma16816(grest[mt][bg * 2 + 1], afr[2][mt], bfr[bg][1], bfr[bg][3]);
                }
        }
        // B-md: pairs (hi,md)->Grest, (md,md)->Grest
        {
            uint32_t bfr[2][4];
            ldsm_x4(bfr[0], b_base + TILEB);
            ldsm_x4(bfr[1], b_base + TILEB + 16 * SROWB);
#pragma unroll
            for (int bg = 0; bg < 2; bg++)
#pragma unroll
                for (int mt = 0; mt < 2; mt++) {
                    mma16816(grest[mt][bg * 2 + 0], afr[0][mt], bfr[bg][0], bfr[bg][2]);
                    mma16816(grest[mt][bg * 2 + 1], afr[0][mt], bfr[bg][1], bfr[bg][3]);
                    mma16816(grest[mt][bg * 2 + 0], afr[1][mt], bfr[bg][0], bfr[bg][2]);
                    mma16816(grest[mt][bg * 2 + 1], afr[1][mt], bfr[bg][1], bfr[bg][3]);
                }
        }
        // B-lo: pair (hi,lo)->Grest
        {
            uint32_t bfr[2][4];
            ldsm_x4(bfr[0], b_base + 2 * TILEB);
            ldsm_x4(bfr[1], b_base + 2 * TILEB + 16 * SROWB);
#pragma unroll
            for (int bg = 0; bg < 2; bg++)
#pragma unroll
                for (int mt = 0; mt < 2; mt++) {
                    mma16816(grest[mt][bg * 2 + 0], afr[0][mt], bfr[bg][0], bfr[bg][2]);
                    mma16816(grest[mt][bg * 2 + 1], afr[0][mt], bfr[bg][1], bfr[bg][3]);
                }
        }
        __syncthreads();
    }

    // epilogue: combine groups (single add), write direct + mirror
    float* Sb = g_S + (size_t)b * NPTS * NPTS;
    const int er = lane >> 2;
    const int ec = (lane & 3) * 2;
#pragma unroll
    for (int mt = 0; mt < 2; mt++) {
#pragma unroll
        for (int nt = 0; nt < 4; nt++) {
            float v0 = ghh[mt][nt][0] + grest[mt][nt][0];
            float v1 = ghh[mt][nt][1] + grest[mt][nt][1];
            float v2 = ghh[mt][nt][2] + grest[mt][nt][2];
            float v3 = ghh[mt][nt][3] + grest[mt][nt][3];
            const int r0 = ti + wm * 32 + mt * 16 + er;
            const int r1 = r0 + 8;
            const int c = tj + wn * 32 + nt * 8 + ec;
            *(float2*)(Sb + (size_t)r0 * NPTS + c) = make_float2(v0, v1);
            *(float2*)(Sb + (size_t)r1 * NPTS + c) = make_float2(v2, v3);
            if (bi != bj) {
                Sb[(size_t)c * NPTS + r0]       = v0;
                Sb[(size_t)(c + 1) * NPTS + r0] = v1;
                Sb[(size_t)c * NPTS + r1]       = v2;
                Sb[(size_t)(c + 1) * NPTS + r1] = v3;
            }
        }
    }
}

// ---------------------------------------------------------------------------
// Kernel 2: exact 32nd-largest via bitwise radix select; one warp per row.
// ---------------------------------------------------------------------------
__global__ __launch_bounds__(256) void select_kernel() {
    const int warp = (blockIdx.x * blockDim.x + threadIdx.x) >> 5;
    const int lane = threadIdx.x & 31;
    const float* Srow = g_S + (size_t)warp * NPTS;

    unsigned u[16];
#pragma unroll
    for (int j = 0; j < 16; j++) {
        unsigned bb = __float_as_uint(Srow[j * 32 + lane]);
        u[j] = (bb & 0x80000000u) ? ~bb : (bb | 0x80000000u);
    }
    unsigned prefix = 0;
#pragma unroll
    for (int bit = 31; bit >= 0; bit--) {
        const unsigned cand = prefix | (1u << bit);
        int c = 0;
#pragma unroll
        for (int j = 0; j < 16; j++) c += (u[j] >= cand);
        c = __reduce_add_sync(0xFFFFFFFFu, c);
        if (c >= KNN) prefix = cand;
    }
    int deg = 0;
#pragma unroll
    for (int j = 0; j < 16; j++) deg += (u[j] >= prefix);
    deg = __reduce_add_sync(0xFFFFFFFFu, deg);

    if (lane == 0) {
        g_thr[warp] = __uint_as_float((prefix & 0x80000000u) ? (prefix ^ 0x80000000u) : ~prefix);
        g_dinv[warp] = rsqrtf((float)deg);
    }
}

// ---------------------------------------------------------------------------
// Kernel 3: out = (S >= thr_i) * dinv_i * dinv_j
// ---------------------------------------------------------------------------
__global__ __launch_bounds__(256) void finalize_kernel(float* __restrict__ out) {
    const size_t q = (size_t)blockIdx.x * blockDim.x + threadIdx.x;
    const size_t base = q * 4;
    const int rowIdx = (int)(base >> 9);
    const int j = (int)(base & 511);
    const int b = rowIdx >> 9;

    const float th = g_thr[rowIdx];
    const float di = g_dinv[rowIdx];
    const float4 s4 = *(const float4*)(g_S + base);
    const float4 d4 = *(const float4*)(g_dinv + (b << 9) + j);

    float4 o;
    o.x = (s4.x >= th) ? di * d4.x : 0.f;
    o.y = (s4.y >= th) ? di * d4.y : 0.f;
    o.z = (s4.z >= th) ? di * d4.z : 0.f;
    o.w = (s4.w >= th) ? di * d4.w : 0.f;
    *(float4*)(out + base) = o;
}

// ---------------------------------------------------------------------------
extern "C" void kernel_launch(void* const* d_in, const int* in_sizes, int n_in,
                              void* d_out, int out_size) {
    const float* x = (const float*)d_in[0];
    float* out = (float*)d_out;

    convert_kernel<<<(BATCH * NPTS * CH) / (256 * 8), 256>>>(x);

    dim3 g1(10, BATCH);
    xxt_mma_kernel<<<g1, 512>>>();

    select_kernel<<<(BATCH * NPTS) / 8, 256>>>();

    const size_t total4 = (size_t)BATCH * NPTS * NPTS / 4;
    finalize_kernel<<<(unsigned)(total4 / 256), 256>>>(out);
}

// round 12
// speedup vs baseline: 1.2622x; 1.2622x over previous
#include <cuda_runtime.h>
#include <cuda_bf16.h>
#include <cstdint>

// Problem constants
#define BATCH 64
#define NPTS  512
#define CH    1024
#define KNN   32

// GEMM geometry: 128x128 CTA tile, 16 warps of 32x32, k-chunk 32, 2-stage pipe
#define KC     32
#define NK0    (CH / KC)        // 32
#define SROWB  80               // smem row stride: 64B data + 16B pad (conflict-free)
#define TILEB  (128 * SROWB)    // 10240 B per split tile
#define STAGEB (6 * TILEB)      // 61440 B per stage
#define SMEMSZ (2 * STAGEB)     // 122880 B

// Scratch (__device__ globals; no allocation)
__device__ float g_S[(size_t)BATCH * NPTS * NPTS];          // 64 MB
__device__ __nv_bfloat16 g_hi[(size_t)BATCH * NPTS * CH];
__device__ __nv_bfloat16 g_md[(size_t)BATCH * NPTS * CH];
__device__ __nv_bfloat16 g_lo[(size_t)BATCH * NPTS * CH];
__device__ float g_thr[BATCH * NPTS];
__device__ float g_dinv[BATCH * NPTS];

// tri tile decode: 10 tiles over 4x4, bi<=bj
__device__ __forceinline__ void tri_decode(int t, int& bi, int& bj) {
    bi = (t >= 4) + (t >= 7) + (t >= 9);
    const int start = bi * 4 - ((bi * (bi - 1)) >> 1);
    bj = bi + (t - start);
}

__device__ __forceinline__ void ldsm_x4(uint32_t* r, uint32_t addr) {
    asm volatile("ldmatrix.sync.aligned.m8n8.x4.shared.b16 {%0,%1,%2,%3}, [%4];"
                 : "=r"(r[0]), "=r"(r[1]), "=r"(r[2]), "=r"(r[3]) : "r"(addr));
}
__device__ __forceinline__ void mma16816(float* d, const uint32_t* a,
                                         uint32_t b0, uint32_t b1) {
    asm volatile(
        "mma.sync.aligned.m16n8k16.row.col.f32.bf16.bf16.f32 "
        "{%0,%1,%2,%3}, {%4,%5,%6,%7}, {%8,%9}, {%0,%1,%2,%3};"
        : "+f"(d[0]), "+f"(d[1]), "+f"(d[2]), "+f"(d[3])
        : "r"(a[0]), "r"(a[1]), "r"(a[2]), "r"(a[3]), "r"(b0), "r"(b1));
}

// async 16B copy gmem->smem
#define CP16(dst, src) \
    asm volatile("cp.async.cg.shared.global [%0], [%1], 16;" :: "r"(dst), "l"(src))
#define CP_COMMIT() asm volatile("cp.async.commit_group;" ::: "memory")
#define CP_WAIT1()  asm volatile("cp.async.wait_group 1;" ::: "memory")
#define CP_WAIT0()  asm volatile("cp.async.wait_group 0;" ::: "memory")

// issue one stage's loads (6 tiles x 128 rows x 64B), 6 x 16B per thread
#define LOAD_STAGE(stage, k0)                                                   \
    do {                                                                        \
        const uint32_t st_ = sb + (stage) * STAGEB;                             \
        _Pragma("unroll")                                                       \
        for (int p_ = 0; p_ < 6; p_++) {                                        \
            const int fid_ = tid + p_ * 512;                                    \
            const int t_ = fid_ >> 9;                                           \
            const int r_ = (fid_ >> 2) & 127;                                   \
            const int q_ = fid_ & 3;                                            \
            const __nv_bfloat16* src_ = sp[t_] + (size_t)r_ * CH + (k0) * KC + q_ * 8; \
            const uint32_t dst_ = st_ + t_ * TILEB + r_ * SROWB + q_ * 16;      \
            CP16(dst_, src_);                                                   \
        }                                                                       \
        CP_COMMIT();                                                            \
    } while (0)

// ---------------------------------------------------------------------------
// Kernel 0: split x into bf16 hi/mid/lo (residuals exact in fp32)
// ---------------------------------------------------------------------------
__global__ __launch_bounds__(256) void convert_kernel(const float* __restrict__ x) {
    const size_t base = ((size_t)blockIdx.x * 256 + threadIdx.x) * 8;
    float v[8];
    *(float4*)&v[0] = *(const float4*)(x + base);
    *(float4*)&v[4] = *(const float4*)(x + base + 4);

    __nv_bfloat16 h[8], m[8], l[8];
#pragma unroll
    for (int i = 0; i < 8; i++) {
        h[i] = __float2bfloat16(v[i]);
        float r1 = v[i] - __bfloat162float(h[i]);
        m[i] = __float2bfloat16(r1);
        float r2 = r1 - __bfloat162float(m[i]);
        l[i] = __float2bfloat16(r2);
    }
    *(uint4*)(g_hi + base) = *(uint4*)h;
    *(uint4*)(g_md + base) = *(uint4*)m;
    *(uint4*)(g_lo + base) = *(uint4*)l;
}

// ---------------------------------------------------------------------------
// Kernel 1: S tri-tile via mma.sync bf16, 6-GEMM split, grouped accumulators
// (Ghh = hi*hi alone at the fp32 ulp floor; Grest = 5 small GEMMs), with a
// 2-stage cp.async pipeline (KC=32) hiding all global-load latency.
// grid = (10, 64), block = 512 (16 warps as 4x4 of 32x32 warp tiles).
// ---------------------------------------------------------------------------
__global__ __launch_bounds__(512) void xxt_mma_kernel() {
    extern __shared__ __align__(16) char smem[];

    const int tid = threadIdx.x;
    const int wid = tid >> 5;
    const int lane = tid & 31;
    const int wm = wid >> 2;          // 0..3  (32-row band)
    const int wn = wid & 3;           // 0..3  (32-col band)

    int bi, bj;
    tri_decode((int)blockIdx.x, bi, bj);
    const int b = blockIdx.y;
    const int ti = bi * 128;
    const int tj = bj * 128;

    const __nv_bfloat16* sp[6];
    {
        const size_t bo = (size_t)b * NPTS * CH;
        sp[0] = g_hi + bo + (size_t)ti * CH;
        sp[1] = g_md + bo + (size_t)ti * CH;
        sp[2] = g_lo + bo + (size_t)ti * CH;
        sp[3] = g_hi + bo + (size_t)tj * CH;
        sp[4] = g_md + bo + (size_t)tj * CH;
        sp[5] = g_lo + bo + (size_t)tj * CH;
    }

    const uint32_t sb = (uint32_t)__cvta_generic_to_shared(smem);
    const int lrow = lane & 15;
    const int lhalf = lane >> 4;
    // intra-tile ldmatrix offsets (stage/tile bases added per use)
    const uint32_t a_off = (uint32_t)((wm * 32 + lrow) * SROWB + lhalf * 16);
    const uint32_t b_off = (uint32_t)(3 * TILEB + (wn * 32 + lrow) * SROWB + lhalf * 16);

    float ghh[2][4][4], grest[2][4][4];
#pragma unroll
    for (int mt = 0; mt < 2; mt++)
#pragma unroll
        for (int nt = 0; nt < 4; nt++)
#pragma unroll
            for (int r = 0; r < 4; r++) { ghh[mt][nt][r] = 0.f; grest[mt][nt][r] = 0.f; }

    // prologue: stage 0 in flight
    LOAD_STAGE(0, 0);

    for (int k0 = 0; k0 < NK0; k0++) {
        if (k0 + 1 < NK0) {
            LOAD_STAGE((k0 + 1) & 1, k0 + 1);
            CP_WAIT1();                // current stage's group done
        } else {
            CP_WAIT0();
        }
        __syncthreads();

        const uint32_t st = sb + (k0 & 1) * STAGEB;
#pragma unroll
        for (int ks = 0; ks < 2; ks++) {
            const uint32_t ko = ks * 32;   // byte offset within 64B row
            uint32_t afr[3][2][4];
#pragma unroll
            for (int s = 0; s < 3; s++) {
                ldsm_x4(afr[s][0], st + a_off + s * TILEB + ko);
                ldsm_x4(afr[s][1], st + a_off + s * TILEB + 16 * SROWB + ko);
            }
            // B-hi: (hi,hi)->Ghh, (md,hi)->Grest, (lo,hi)->Grest
            {
                uint32_t bfr[2][4];
                ldsm_x4(bfr[0], st + b_off + ko);
                ldsm_x4(bfr[1], st + b_off + 16 * SROWB + ko);
#pragma unroll
                for (int bg = 0; bg < 2; bg++)
#pragma unroll
                    for (int mt = 0; mt < 2; mt++) {
                        mma16816(ghh[mt][bg * 2 + 0], afr[0][mt], bfr[bg][0], bfr[bg][2]);
                        mma16816(ghh[mt][bg * 2 + 1], afr[0][mt], bfr[bg][1], bfr[bg][3]);
                        mma16816(grest[mt][bg * 2 + 0], afr[1][mt], bfr[bg][0], bfr[bg][2]);
                        mma16816(grest[mt][bg * 2 + 1], afr[1][mt], bfr[bg][1], bfr[bg][3]);
                        mma16816(grest[mt][bg * 2 + 0], afr[2][mt], bfr[bg][0], bfr[bg][2]);
                        mma16816(grest[mt][bg * 2 + 1], afr[2][mt], bfr[bg][1], bfr[bg][3]);
                    }
            }
            // B-md: (hi,md)->Grest, (md,md)->Grest
            {
                uint32_t bfr[2][4];
                ldsm_x4(bfr[0], st + b_off + TILEB + ko);
                ldsm_x4(bfr[1], st + b_off + TILEB + 16 * SROWB + ko);
#pragma unroll
                for (int bg = 0; bg < 2; bg++)
#pragma unroll
                    for (int mt = 0; mt < 2; mt++) {
                        mma16816(grest[mt][bg * 2 + 0], afr[0][mt], bfr[bg][0], bfr[bg][2]);
                        mma16816(grest[mt][bg * 2 + 1], afr[0][mt], bfr[bg][1], bfr[bg][3]);
                        mma16816(grest[mt][bg * 2 + 0], afr[1][mt], bfr[bg][0], bfr[bg][2]);
                        mma16816(grest[mt][bg * 2 + 1], afr[1][mt], bfr[bg][1], bfr[bg][3]);
                    }
            }
            // B-lo: (hi,lo)->Grest
            {
                uint32_t bfr[2][4];
                ldsm_x4(bfr[0], st + b_off + 2 * TILEB + ko);
                ldsm_x4(bfr[1], st + b_off + 2 * TILEB + 16 * SROWB + ko);
#pragma unroll
                for (int bg = 0; bg < 2; bg++)
#pragma unroll
                    for (int mt = 0; mt < 2; mt++) {
                        mma16816(grest[mt][bg * 2 + 0], afr[0][mt], bfr[bg][0], bfr[bg][2]);
                        mma16816(grest[mt][bg * 2 + 1], afr[0][mt], bfr[bg][1], bfr[bg][3]);
                    }
            }
        }
        __syncthreads();   // all warps done with this stage before it is refilled
    }

    // epilogue: combine groups (single add), write direct + mirror
    float* Sb = g_S + (size_t)b * NPTS * NPTS;
    const int er = lane >> 2;
    const int ec = (lane & 3) * 2;
#pragma unroll
    for (int mt = 0; mt < 2; mt++) {
#pragma unroll
        for (int nt = 0; nt < 4; nt++) {
            float v0 = ghh[mt][nt][0] + grest[mt][nt][0];
            float v1 = ghh[mt][nt][1] + grest[mt][nt][1];
            float v2 = ghh[mt][nt][2] + grest[mt][nt][2];
            float v3 = ghh[mt][nt][3] + grest[mt][nt][3];
            const int r0 = ti + wm * 32 + mt * 16 + er;
            const int r1 = r0 + 8;
            const int c = tj + wn * 32 + nt * 8 + ec;
            *(float2*)(Sb + (size_t)r0 * NPTS + c) = make_float2(v0, v1);
            *(float2*)(Sb + (size_t)r1 * NPTS + c) = make_float2(v2, v3);
            if (bi != bj) {
                Sb[(size_t)c * NPTS + r0]       = v0;
                Sb[(size_t)(c + 1) * NPTS + r0] = v1;
                Sb[(size_t)c * NPTS + r1]       = v2;
                Sb[(size_t)(c + 1) * NPTS + r1] = v3;
            }
        }
    }
}

// ---------------------------------------------------------------------------
// Kernel 2: exact 32nd-largest via bitwise radix select; one warp per row.
// ---------------------------------------------------------------------------
__global__ __launch_bounds__(256) void select_kernel() {
    const int warp = (blockIdx.x * blockDim.x + threadIdx.x) >> 5;
    const int lane = threadIdx.x & 31;
    const float* Srow = g_S + (size_t)warp * NPTS;

    unsigned u[16];
#pragma unroll
    for (int j = 0; j < 16; j++) {
        unsigned bb = __float_as_uint(Srow[j * 32 + lane]);
        u[j] = (bb & 0x80000000u) ? ~bb : (bb | 0x80000000u);
    }
    unsigned prefix = 0;
#pragma unroll
    for (int bit = 31; bit >= 0; bit--) {
        const unsigned cand = prefix | (1u << bit);
        int c = 0;
#pragma unroll
        for (int j = 0; j < 16; j++) c += (u[j] >= cand);
        c = __reduce_add_sync(0xFFFFFFFFu, c);
        if (c >= KNN) prefix = cand;
    }
    int deg = 0;
#pragma unroll
    for (int j = 0; j < 16; j++) deg += (u[j] >= prefix);
    deg = __reduce_add_sync(0xFFFFFFFFu, deg);

    if (lane == 0) {
        g_thr[warp] = __uint_as_float((prefix & 0x80000000u) ? (prefix ^ 0x80000000u) : ~prefix);
        g_dinv[warp] = rsqrtf((float)deg);
    }
}

// ---------------------------------------------------------------------------
// Kernel 3: out = (S >= thr_i) * dinv_i * dinv_j
// ---------------------------------------------------------------------------
__global__ __launch_bounds__(256) void finalize_kernel(float* __restrict__ out) {
    const size_t q = (size_t)blockIdx.x * blockDim.x + threadIdx.x;
    const size_t base = q * 4;
    const int rowIdx = (int)(base >> 9);
    const int j = (int)(base & 511);
    const int b = rowIdx >> 9;

    const float th = g_thr[rowIdx];
    const float di = g_dinv[rowIdx];
    const float4 s4 = *(const float4*)(g_S + base);
    const float4 d4 = *(const float4*)(g_dinv + (b << 9) + j);

    float4 o;
    o.x = (s4.x >= th) ? di * d4.x : 0.f;
    o.y = (s4.y >= th) ? di * d4.y : 0.f;
    o.z = (s4.z >= th) ? di * d4.z : 0.f;
    o.w = (s4.w >= th) ? di * d4.w : 0.f;
    *(float4*)(out + base) = o;
}

// ---------------------------------------------------------------------------
extern "C" void kernel_launch(void* const* d_in, const int* in_sizes, int n_in,
                              void* d_out, int out_size) {
    const float* x = (const float*)d_in[0];
    float* out = (float*)d_out;

    cudaFuncSetAttribute(xxt_mma_kernel,
                         cudaFuncAttributeMaxDynamicSharedMemorySize, SMEMSZ);

    convert_kernel<<<(BATCH * NPTS * CH) / (256 * 8), 256>>>(x);

    dim3 g1(10, BATCH);
    xxt_mma_kernel<<<g1, 512, SMEMSZ>>>();

    select_kernel<<<(BATCH * NPTS) / 8, 256>>>();

    const size_t total4 = (size_t)BATCH * NPTS * NPTS / 4;
    finalize_kernel<<<(unsigned)(total4 / 256), 256>>>(out);
}

// round 15
// speedup vs baseline: 1.3268x; 1.0512x over previous
#include <cuda_runtime.h>
#include <cuda_bf16.h>
#include <cstdint>

// Problem constants
#define BATCH 64
#define NPTS  512
#define CH    1024
#define KNN   32

// GEMM geometry: 128x64 CTA tile, 8 warps of 32x32, k-chunk 32, 2-stage pipe
#define KC     32
#define NK0    (CH / KC)        // 32
#define SROWB  80               // smem row stride: 64B data + 16B pad
#define A_TILEB (128 * SROWB)   // 10240 B
#define B_TILEB (64 * SROWB)    // 5120 B
#define STAGEB (3 * A_TILEB + 3 * B_TILEB)   // 46080 B
#define SMEMSZ (2 * STAGEB)                   // 92160 B

// Scratch (__device__ globals; no allocation)
__device__ float g_S[(size_t)BATCH * NPTS * NPTS];          // 64 MB
__device__ __nv_bfloat16 g_hi[(size_t)BATCH * NPTS * CH];
__device__ __nv_bfloat16 g_md[(size_t)BATCH * NPTS * CH];
__device__ __nv_bfloat16 g_lo[(size_t)BATCH * NPTS * CH];
__device__ float g_thr[BATCH * NPTS];
__device__ float g_dinv[BATCH * NPTS];

__device__ __forceinline__ void ldsm_x4(uint32_t* r, uint32_t addr) {
    asm volatile("ldmatrix.sync.aligned.m8n8.x4.shared.b16 {%0,%1,%2,%3}, [%4];"
                 : "=r"(r[0]), "=r"(r[1]), "=r"(r[2]), "=r"(r[3]) : "r"(addr));
}
__device__ __forceinline__ void mma16816(float* d, const uint32_t* a,
                                         uint32_t b0, uint32_t b1) {
    asm volatile(
        "mma.sync.aligned.m16n8k16.row.col.f32.bf16.bf16.f32 "
        "{%0,%1,%2,%3}, {%4,%5,%6,%7}, {%8,%9}, {%0,%1,%2,%3};"
        : "+f"(d[0]), "+f"(d[1]), "+f"(d[2]), "+f"(d[3])
        : "r"(a[0]), "r"(a[1]), "r"(a[2]), "r"(a[3]), "r"(b0), "r"(b1));
}

#define CP16(dst, src) \
    asm volatile("cp.async.cg.shared.global [%0], [%1], 16;" :: "r"(dst), "l"(src))
#define CP_COMMIT() asm volatile("cp.async.commit_group;" ::: "memory")
#define CP_WAIT1()  asm volatile("cp.async.wait_group 1;" ::: "memory")
#define CP_WAIT0()  asm volatile("cp.async.wait_group 0;" ::: "memory")

// one stage's loads: A = 3 tiles x 128 rows x 4 x 16B, B = 3 tiles x 64 rows x 4 x 16B
// 2304 chunks / 256 threads = 9 per thread (p<6 -> A, else B; branch compile-time)
#define LOAD_STAGE(stage, k0)                                                    \
    do {                                                                         \
        const uint32_t st_ = sb + (stage) * STAGEB;                              \
        _Pragma("unroll")                                                        \
        for (int p_ = 0; p_ < 9; p_++) {                                         \
            if (p_ < 6) {                                                        \
                const int fid_ = tid + p_ * 256;      /* 0..1535 */              \
                const int t_ = fid_ >> 9;                                        \
                const int r_ = (fid_ >> 2) & 127;                                \
                const int q_ = fid_ & 3;                                         \
                CP16(st_ + t_ * A_TILEB + r_ * SROWB + q_ * 16,                  \
                     spA[t_] + (size_t)r_ * CH + (k0) * KC + q_ * 8);            \
            } else {                                                             \
                const int g_ = tid + (p_ - 6) * 256;  /* 0..767 */               \
                const int t_ = g_ >> 8;                                          \
                const int r_ = (g_ >> 2) & 63;                                   \
                const int q_ = g_ & 3;                                           \
                CP16(st_ + 3 * A_TILEB + t_ * B_TILEB + r_ * SROWB + q_ * 16,    \
                     spB[t_] + (size_t)r_ * CH + (k0) * KC + q_ * 8);            \
            }                                                                    \
        }                                                                        \
        CP_COMMIT();                                                             \
    } while (0)

// ---------------------------------------------------------------------------
// Kernel 0: split x into bf16 hi/mid/lo (residuals exact in fp32)
// ---------------------------------------------------------------------------
__global__ __launch_bounds__(256) void convert_kernel(const float* __restrict__ x) {
    const size_t base = ((size_t)blockIdx.x * 256 + threadIdx.x) * 8;
    float v[8];
    *(float4*)&v[0] = *(const float4*)(x + base);
    *(float4*)&v[4] = *(const float4*)(x + base + 4);

    __nv_bfloat16 h[8], m[8], l[8];
#pragma unroll
    for (int i = 0; i < 8; i++) {
        h[i] = __float2bfloat16(v[i]);
        float r1 = v[i] - __bfloat162float(h[i]);
        m[i] = __float2bfloat16(r1);
        float r2 = r1 - __bfloat162float(m[i]);
        l[i] = __float2bfloat16(r2);
    }
    *(uint4*)(g_hi + base) = *(uint4*)h;
    *(uint4*)(g_md + base) = *(uint4*)m;
    *(uint4*)(g_lo + base) = *(uint4*)l;
}

// ---------------------------------------------------------------------------
// Kernel 1: S via mma.sync bf16, 6-GEMM split, grouped accumulators
// (Ghh = hi*hi alone; Grest = 5 small GEMMs), 2-stage cp.async pipeline.
// 128x64 tri-tiles (cj >= 2*bi, 20/batch), 256 thr = 8 warps of 32x32.
// Mirror: element (r,c) mirrored to (c,r) iff (r>>6) < (cj & ~1)  [R7 proof].
// ---------------------------------------------------------------------------
__global__ __launch_bounds__(256, 2) void xxt_mma_kernel() {
    extern __shared__ __align__(16) char smem[];

    const int tid = threadIdx.x;
    const int wid = tid >> 5;
    const int lane = tid & 31;
    const int wm = wid >> 1;          // 0..3  (32-row band)
    const int wn = wid & 1;           // 0..1  (32-col band)

    const int t = blockIdx.x;         // 0..19
    const int b = blockIdx.y;
    const int bi = (t >= 8) + (t >= 14) + (t >= 18);
    const int cj = t - bi * (9 - bi) + 2 * bi;
    const int ti = bi * 128;
    const int tj = cj * 64;

    const __nv_bfloat16 *spA[3], *spB[3];
    {
        const size_t bo = (size_t)b * NPTS * CH;
        spA[0] = g_hi + bo + (size_t)ti * CH;
        spA[1] = g_md + bo + (size_t)ti * CH;
        spA[2] = g_lo + bo + (size_t)ti * CH;
        spB[0] = g_hi + bo + (size_t)tj * CH;
        spB[1] = g_md + bo + (size_t)tj * CH;
        spB[2] = g_lo + bo + (size_t)tj * CH;
    }

    const uint32_t sb = (uint32_t)__cvta_generic_to_shared(smem);
    const int lrow = lane & 15;
    const int lhalf = lane >> 4;
    const uint32_t a_off = (uint32_t)((wm * 32 + lrow) * SROWB + lhalf * 16);
    const uint32_t b_off = (uint32_t)(3 * A_TILEB + (wn * 32 + lrow) * SROWB + lhalf * 16);

    float ghh[2][4][4], grest[2][4][4];
#pragma unroll
    for (int mt = 0; mt < 2; mt++)
#pragma unroll
        for (int nt = 0; nt < 4; nt++)
#pragma unroll
            for (int r = 0; r < 4; r++) { ghh[mt][nt][r] = 0.f; grest[mt][nt][r] = 0.f; }

    LOAD_STAGE(0, 0);

    for (int k0 = 0; k0 < NK0; k0++) {
        if (k0 + 1 < NK0) {
            LOAD_STAGE((k0 + 1) & 1, k0 + 1);
            CP_WAIT1();
        } else {
            CP_WAIT0();
        }
        __syncthreads();

        const uint32_t st = sb + (k0 & 1) * STAGEB;
#pragma unroll
        for (int ks = 0; ks < 2; ks++) {
            const uint32_t ko = ks * 32;
            uint32_t afr[3][2][4];
#pragma unroll
            for (int s = 0; s < 3; s++) {
                ldsm_x4(afr[s][0], st + a_off + s * A_TILEB + ko);
                ldsm_x4(afr[s][1], st + a_off + s * A_TILEB + 16 * SROWB + ko);
            }
            // B-hi: (hi,hi)->Ghh, (md,hi)->Grest, (lo,hi)->Grest
            {
                uint32_t bfr[2][4];
                ldsm_x4(bfr[0], st + b_off + ko);
                ldsm_x4(bfr[1], st + b_off + 16 * SROWB + ko);
#pragma unroll
                for (int bg = 0; bg < 2; bg++)
#pragma unroll
                    for (int mt = 0; mt < 2; mt++) {
                        mma16816(ghh[mt][bg * 2 + 0], afr[0][mt], bfr[bg][0], bfr[bg][2]);
                        mma16816(ghh[mt][bg * 2 + 1], afr[0][mt], bfr[bg][1], bfr[bg][3]);
                        mma16816(grest[mt][bg * 2 + 0], afr[1][mt], bfr[bg][0], bfr[bg][2]);
                        mma16816(grest[mt][bg * 2 + 1], afr[1][mt], bfr[bg][1], bfr[bg][3]);
                        mma16816(grest[mt][bg * 2 + 0], afr[2][mt], bfr[bg][0], bfr[bg][2]);
                        mma16816(grest[mt][bg * 2 + 1], afr[2][mt], bfr[bg][1], bfr[bg][3]);
                    }
            }
            // B-md: (hi,md)->Grest, (md,md)->Grest
            {
                uint32_t bfr[2][4];
                ldsm_x4(bfr[0], st + b_off + B_TILEB + ko);
                ldsm_x4(bfr[1], st + b_off + B_TILEB + 16 * SROWB + ko);
#pragma unroll
                for (int bg = 0; bg < 2; bg++)
#pragma unroll
                    for (int mt = 0; mt < 2; mt++) {
                        mma16816(grest[mt][bg * 2 + 0], afr[0][mt], bfr[bg][0], bfr[bg][2]);
                        mma16816(grest[mt][bg * 2 + 1], afr[0][mt], bfr[bg][1], bfr[bg][3]);
                        mma16816(grest[mt][bg * 2 + 0], afr[1][mt], bfr[bg][0], bfr[bg][2]);
                        mma16816(grest[mt][bg * 2 + 1], afr[1][mt], bfr[bg][1], bfr[bg][3]);
                    }
            }
            // B-lo: (hi,lo)->Grest
            {
                uint32_t bfr[2][4];
                ldsm_x4(bfr[0], st + b_off + 2 * B_TILEB + ko);
                ldsm_x4(bfr[1], st + b_off + 2 * B_TILEB + 16 * SROWB + ko);
#pragma unroll
                for (int bg = 0; bg < 2; bg++)
#pragma unroll
                    for (int mt = 0; mt < 2; mt++) {
                        mma16816(grest[mt][bg * 2 + 0], afr[0][mt], bfr[bg][0], bfr[bg][2]);
                        mma16816(grest[mt][bg * 2 + 1], afr[0][mt], bfr[bg][1], bfr[bg][3]);
                    }
            }
        }
        __syncthreads();
    }

    // epilogue: combine groups, write direct + predicated mirror
    float* Sb = g_S + (size_t)b * NPTS * NPTS;
    const int er = lane >> 2;
    const int ec = (lane & 3) * 2;
    const bool mirror = (2 * bi + (wm >> 1)) < (cj & ~1);
#pragma unroll
    for (int mt = 0; mt < 2; mt++) {
#pragma unroll
        for (int nt = 0; nt < 4; nt++) {
            float v0 = ghh[mt][nt][0] + grest[mt][nt][0];
            float v1 = ghh[mt][nt][1] + grest[mt][nt][1];
            float v2 = ghh[mt][nt][2] + grest[mt][nt][2];
            float v3 = ghh[mt][nt][3] + grest[mt][nt][3];
            const int r0 = ti + wm * 32 + mt * 16 + er;
            const int r1 = r0 + 8;
            const int c = tj + wn * 32 + nt * 8 + ec;
            *(float2*)(Sb + (size_t)r0 * NPTS + c) = make_float2(v0, v1);
            *(float2*)(Sb + (size_t)r1 * NPTS + c) = make_float2(v2, v3);
            if (mirror) {
                Sb[(size_t)c * NPTS + r0]       = v0;
                Sb[(size_t)(c + 1) * NPTS + r0] = v1;
                Sb[(size_t)c * NPTS + r1]       = v2;
                Sb[(size_t)(c + 1) * NPTS + r1] = v3;
            }
        }
    }
}

// ---------------------------------------------------------------------------
// Kernel 2: exact 32nd-largest via bitwise radix select; one warp per row.
// ---------------------------------------------------------------------------
__global__ __launch_bounds__(256) void select_kernel() {
    const int warp = (blockIdx.x * blockDim.x + threadIdx.x) >> 5;
    const int lane = threadIdx.x & 31;
    const float* Srow = g_S + (size_t)warp * NPTS;

    unsigned u[16];
#pragma unroll
    for (int j = 0; j < 16; j++) {
        unsigned bb = __float_as_uint(Srow[j * 32 + lane]);
        u[j] = (bb & 0x80000000u) ? ~bb : (bb | 0x80000000u);
    }
    unsigned prefix = 0;
#pragma unroll
    for (int bit = 31; bit >= 0; bit--) {
        const unsigned cand = prefix | (1u << bit);
        int c = 0;
#pragma unroll
        for (int j = 0; j < 16; j++) c += (u[j] >= cand);
        c = __reduce_add_sync(0xFFFFFFFFu, c);
        if (c >= KNN) prefix = cand;
    }
    int deg = 0;
#pragma unroll
    for (int j = 0; j < 16; j++) deg += (u[j] >= prefix);
    deg = __reduce_add_sync(0xFFFFFFFFu, deg);

    if (lane == 0) {
        g_thr[warp] = __uint_as_float((prefix & 0x80000000u) ? (prefix ^ 0x80000000u) : ~prefix);
        g_dinv[warp] = rsqrtf((float)deg);
    }
}

// ---------------------------------------------------------------------------
// Kernel 3: out = (S >= thr_i) * dinv_i * dinv_j
// ---------------------------------------------------------------------------
__global__ __launch_bounds__(256) void finalize_kernel(float* __restrict__ out) {
    const size_t q = (size_t)blockIdx.x * blockDim.x + threadIdx.x;
    const size_t base = q * 4;
    const int rowIdx = (int)(base >> 9);
    const int j = (int)(base & 511);
    const int b = rowIdx >> 9;

    const float th = g_thr[rowIdx];
    const float di = g_dinv[rowIdx];
    const float4 s4 = *(const float4*)(g_S + base);
    const float4 d4 = *(const float4*)(g_dinv + (b << 9) + j);

    float4 o;
    o.x = (s4.x >= th) ? di * d4.x : 0.f;
    o.y = (s4.y >= th) ? di * d4.y : 0.f;
    o.z = (s4.z >= th) ? di * d4.z : 0.f;
    o.w = (s4.w >= th) ? di * d4.w : 0.f;
    *(float4*)(out + base) = o;
}

// ---------------------------------------------------------------------------
extern "C" void kernel_launch(void* const* d_in, const int* in_sizes, int n_in,
                              void* d_out, int out_size) {
    const float* x = (const float*)d_in[0];
    float* out = (float*)d_out;

    cudaFuncSetAttribute(xxt_mma_kernel,
                         cudaFuncAttributeMaxDynamicSharedMemorySize, SMEMSZ);

    convert_kernel<<<(BATCH * NPTS * CH) / (256 * 8), 256>>>(x);

    dim3 g1(20, BATCH);                // 20 tri-tiles x 64 batches
    xxt_mma_kernel<<<g1, 256, SMEMSZ>>>();

    select_kernel<<<(BATCH * NPTS) / 8, 256>>>();

    const size_t total4 = (size_t)BATCH * NPTS * NPTS / 4;
    finalize_kernel<<<(unsigned)(total4 / 256), 256>>>(out);
}